// round 6
// baseline (speedup 1.0000x reference)
#include <cuda_runtime.h>
#include <cuda_fp16.h>
#include <cstdint>

#define TOKENS 8192
#define DIN    4096
#define DOUT   4096
#define NFAC   2
#define RANK   64

// scratch (static __device__ globals; no allocation)
__device__ __half g_xh[(size_t)TOKENS * DIN];
__device__ __half g_weff[(size_t)DOUT * DIN];
__device__ __half g_abh[(size_t)DOUT * (NFAC * RANK)];
__device__ __half g_ch[(size_t)DIN * (NFAC * RANK)];

__device__ __forceinline__ uint32_t smem_u32(const void* p) {
    uint32_t a;
    asm("{ .reg .u64 t; cvta.to.shared.u64 t, %1; cvt.u32.u64 %0, t; }" : "=r"(a) : "l"(p));
    return a;
}
__device__ __forceinline__ void cp16(uint32_t dst, const void* src) {
    asm volatile("cp.async.cg.shared.global [%0], [%1], 16;" :: "r"(dst), "l"(src) : "memory");
}
#define SWZ(o) ((o) ^ (((o) >> 3) & 0x70))

__device__ __forceinline__ void ldsm4(uint32_t* r, uint32_t addr) {
    asm volatile("ldmatrix.sync.aligned.m8n8.x4.shared.b16 {%0,%1,%2,%3}, [%4];"
                 : "=r"(r[0]), "=r"(r[1]), "=r"(r[2]), "=r"(r[3]) : "r"(addr));
}
__device__ __forceinline__ void hmma(float* c, const uint32_t* a, uint32_t b0, uint32_t b1) {
    asm volatile(
        "mma.sync.aligned.m16n8k16.row.col.f32.f16.f16.f32 "
        "{%0,%1,%2,%3}, {%4,%5,%6,%7}, {%8,%9}, {%0,%1,%2,%3};"
        : "+f"(c[0]), "+f"(c[1]), "+f"(c[2]), "+f"(c[3])
        : "r"(a[0]), "r"(a[1]), "r"(a[2]), "r"(a[3]), "r"(b0), "r"(b1));
}

// abh[o, f*64+k] = fp16( sum_r tanh(A[f,o,r]) * B[f,r,k] )
__global__ void prep_ab(const float* __restrict__ As, const float* __restrict__ Bs,
                        __half* __restrict__ abh) {
    int o = blockIdx.x, f = blockIdx.y, k = threadIdx.x;
    __shared__ float ta[RANK];
    ta[k] = tanhf(As[((size_t)f * DOUT + o) * RANK + k]);
    __syncthreads();
    const float* Bf = Bs + (size_t)f * RANK * RANK;
    float acc = 0.f;
    #pragma unroll 8
    for (int r = 0; r < RANK; ++r) acc += ta[r] * Bf[r * RANK + k];
    abh[(size_t)o * (NFAC * RANK) + f * RANK + k] = __float2half_rn(acc);
}

// ch[i, f*64+k] = fp16( C[f,k,i] )
__global__ void conv_c(const float* __restrict__ Cs, __half* __restrict__ ch) {
    int idx = blockIdx.x * 256 + threadIdx.x;
    int i = idx & (DIN - 1);
    int fk = idx >> 12;
    ch[(size_t)i * (NFAC * RANK) + fk] = __float2half_rn(Cs[idx]);
}

__global__ void conv_x(const float4* __restrict__ xi, __half2* __restrict__ xo) {
    size_t i = (size_t)blockIdx.x * 256 + threadIdx.x;
    float4 v = xi[i];
    xo[2 * i]     = __floats2half2_rn(v.x, v.y);
    xo[2 * i + 1] = __floats2half2_rn(v.z, v.w);
}

// D[BMxBN] tile of A[M,K] @ B[N,K]^T, fp16 in / fp32 accum.
// EPI 0: fp32 out, += bias[n].  EPI 1: fp16 out, += addv[m,n] (full matrix).
template<int KTOT, int EPI>
__global__ void __launch_bounds__(256, 1)
gemm_hmma(const __half* __restrict__ A, const __half* __restrict__ B,
          const float* __restrict__ addv, void* __restrict__ outp, int ldo)
{
    constexpr int BM = 128, BN = 256, BK = 64, S = 3;
    constexpr int NCH = KTOT / BK;
    constexpr int ABYTES = BM * 128;          // 16 KB (128 rows x 128 B of K)
    constexpr int BBYTES = BN * 128;          // 32 KB
    constexpr int STAGE = ABYTES + BBYTES;    // 48 KB

    extern __shared__ char smraw[];
    uint32_t sbase = (smem_u32(smraw) + 1023) & ~1023u;

    const int tid = threadIdx.x, wid = tid >> 5, lane = tid & 31;
    const int wm = wid & 1, wn = wid >> 1;    // 2 x 4 warp grid, 64x64 per warp
    const int m0 = blockIdx.y * BM, n0 = blockIdx.x * BN;
    const __half* Ab = A + (size_t)m0 * KTOT;
    const __half* Bb = B + (size_t)n0 * KTOT;

    auto load_chunk = [&](int p) {
        uint32_t s = sbase + (p % S) * STAGE;
        const __half* Ap = Ab + p * BK;
        const __half* Bp = Bb + p * BK;
        #pragma unroll
        for (int it = 0; it < 4; ++it) {      // A: 128 rows x 8 segs = 1024 cp16
            int idx = tid + it * 256;
            int r = idx >> 3, sg = idx & 7;
            cp16(s + SWZ((uint32_t)(r * 128 + sg * 16)), Ap + (size_t)r * KTOT + sg * 8);
        }
        #pragma unroll
        for (int it = 0; it < 8; ++it) {      // B: 256 rows x 8 segs = 2048 cp16
            int idx = tid + it * 256;
            int r = idx >> 3, sg = idx & 7;
            cp16(s + ABYTES + SWZ((uint32_t)(r * 128 + sg * 16)),
                 Bp + (size_t)r * KTOT + sg * 8);
        }
    };

    float acc[4][8][4];
    #pragma unroll
    for (int t = 0; t < 4; ++t)
        #pragma unroll
        for (int j = 0; j < 8; ++j)
            #pragma unroll
            for (int q = 0; q < 4; ++q) acc[t][j][q] = 0.f;

    #pragma unroll
    for (int p = 0; p < S - 1; ++p) {
        if (p < NCH) load_chunk(p);
        asm volatile("cp.async.commit_group;" ::: "memory");
    }

    const int la = lane & 15, lb = lane >> 4;

    for (int c = 0; c < NCH; ++c) {
        asm volatile("cp.async.wait_group %0;" :: "n"(S - 2) : "memory");
        __syncthreads();
        int p = c + S - 1;
        if (p < NCH) load_chunk(p);
        asm volatile("cp.async.commit_group;" ::: "memory");

        uint32_t sA = sbase + (c % S) * STAGE;
        uint32_t sB = sA + ABYTES;
        #pragma unroll
        for (int ks = 0; ks < 4; ++ks) {      // K = 4 x 16
            uint32_t af[4][4], bf[4][4];
            #pragma unroll
            for (int t = 0; t < 4; ++t) {
                uint32_t row = (uint32_t)(wm * 64 + t * 16 + la);
                ldsm4(af[t], sA + SWZ(row * 128 + (uint32_t)(ks * 32 + lb * 16)));
            }
            #pragma unroll
            for (int u = 0; u < 4; ++u) {
                uint32_t row = (uint32_t)(wn * 64 + u * 16 + la);
                ldsm4(bf[u], sB + SWZ(row * 128 + (uint32_t)(ks * 32 + lb * 16)));
            }
            #pragma unroll
            for (int t = 0; t < 4; ++t)
                #pragma unroll
                for (int u = 0; u < 4; ++u) {
                    hmma(acc[t][2 * u],     af[t], bf[u][0], bf[u][2]);
                    hmma(acc[t][2 * u + 1], af[t], bf[u][1], bf[u][3]);
                }
        }
    }

    // epilogue (register accumulators -> global)
    const int r0 = lane >> 2, c0 = (lane & 3) * 2;
    #pragma unroll
    for (int t = 0; t < 4; ++t) {
        #pragma unroll
        for (int h = 0; h < 2; ++h) {
            size_t row = (size_t)(m0 + wm * 64 + t * 16 + h * 8 + r0);
            #pragma unroll
            for (int j = 0; j < 8; ++j) {
                int col = n0 + wn * 64 + j * 8 + c0;
                float v0 = acc[t][j][h * 2 + 0], v1 = acc[t][j][h * 2 + 1];
                if (EPI == 0) {
                    float2 w;
                    w.x = v0 + addv[col];
                    w.y = v1 + addv[col + 1];
                    *(float2*)((float*)outp + row * (size_t)ldo + col) = w;
                } else {
                    const float* wr = addv + row * (size_t)ldo + col;
                    *(__half2*)((__half*)outp + row * (size_t)ldo + col) =
                        __floats2half2_rn(v0 + wr[0], v1 + wr[1]);
                }
            }
        }
    }
}

extern "C" void kernel_launch(void* const* d_in, const int* in_sizes, int n_in,
                              void* d_out, int out_size) {
    (void)in_sizes; (void)n_in; (void)out_size;
    const float* x    = (const float*)d_in[0];
    const float* W    = (const float*)d_in[1];
    const float* bias = (const float*)d_in[2];
    const float* As   = (const float*)d_in[3];
    const float* Bs   = (const float*)d_in[4];
    const float* Cs   = (const float*)d_in[5];

    __half *xh, *weff, *abh, *ch;
    cudaGetSymbolAddress((void**)&xh,   g_xh);
    cudaGetSymbolAddress((void**)&weff, g_weff);
    cudaGetSymbolAddress((void**)&abh,  g_abh);
    cudaGetSymbolAddress((void**)&ch,   g_ch);

    const int SMEM_SZ = 1024 + 3 * (128 * 128 + 256 * 128);  // 148480 B
    cudaFuncSetAttribute(gemm_hmma<128, 1>,
                         cudaFuncAttributeMaxDynamicSharedMemorySize, SMEM_SZ);
    cudaFuncSetAttribute(gemm_hmma<4096, 0>,
                         cudaFuncAttributeMaxDynamicSharedMemorySize, SMEM_SZ);

    prep_ab<<<dim3(DOUT, NFAC), RANK>>>(As, Bs, abh);
    conv_c<<<(NFAC * RANK * DIN) / 256, 256>>>(Cs, ch);
    conv_x<<<(TOKENS * (DIN / 4)) / 256, 256>>>((const float4*)x, (__half2*)xh);
    // W_eff = W + abh @ ch^T   (M=DOUT, N=DIN, K=128), fp16 out
    gemm_hmma<128, 1><<<dim3(DIN / 256, DOUT / 128), 256, SMEM_SZ>>>(
        abh, ch, W, (void*)weff, DIN);
    // out = xh @ weff^T + bias (M=TOKENS, N=DOUT, K=DIN), fp32 out
    gemm_hmma<4096, 0><<<dim3(DOUT / 256, TOKENS / 128), 256, SMEM_SZ>>>(
        xh, weff, bias, d_out, DOUT);
}

// round 7
// speedup vs baseline: 1.0300x; 1.0300x over previous
#include <cuda_runtime.h>
#include <cuda_fp16.h>
#include <cstdint>

#define TOKENS 8192
#define DIN    4096
#define DOUT   4096
#define NFAC   2
#define RANK   64

// scratch (static __device__ globals; no allocation)
__device__ __half g_xh[(size_t)TOKENS * DIN];
__device__ __half g_weff[(size_t)DOUT * DIN];
__device__ __half g_abh[(size_t)DOUT * (NFAC * RANK)];
__device__ __half g_ch[(size_t)DIN * (NFAC * RANK)];

__device__ __forceinline__ uint32_t smem_u32(const void* p) {
    uint32_t a;
    asm("{ .reg .u64 t; cvta.to.shared.u64 t, %1; cvt.u32.u64 %0, t; }" : "=r"(a) : "l"(p));
    return a;
}
__device__ __forceinline__ void cp16(uint32_t dst, const void* src) {
    asm volatile("cp.async.cg.shared.global [%0], [%1], 16;" :: "r"(dst), "l"(src) : "memory");
}
#define SWZ(o) ((o) ^ (((o) >> 3) & 0x70))

__device__ __forceinline__ void ldsm4(uint32_t* r, uint32_t addr) {
    asm volatile("ldmatrix.sync.aligned.m8n8.x4.shared.b16 {%0,%1,%2,%3}, [%4];"
                 : "=r"(r[0]), "=r"(r[1]), "=r"(r[2]), "=r"(r[3]) : "r"(addr));
}
__device__ __forceinline__ void hmma(float* c, const uint32_t* a, uint32_t b0, uint32_t b1) {
    asm volatile(
        "mma.sync.aligned.m16n8k16.row.col.f32.f16.f16.f32 "
        "{%0,%1,%2,%3}, {%4,%5,%6,%7}, {%8,%9}, {%0,%1,%2,%3};"
        : "+f"(c[0]), "+f"(c[1]), "+f"(c[2]), "+f"(c[3])
        : "r"(a[0]), "r"(a[1]), "r"(a[2]), "r"(a[3]), "r"(b0), "r"(b1));
}

// abh[o, f*64+k] = fp16( sum_r tanh(A[f,o,r]) * B[f,r,k] )
__global__ void prep_ab(const float* __restrict__ As, const float* __restrict__ Bs,
                        __half* __restrict__ abh) {
    int o = blockIdx.x, f = blockIdx.y, k = threadIdx.x;
    __shared__ float ta[RANK];
    ta[k] = tanhf(As[((size_t)f * DOUT + o) * RANK + k]);
    __syncthreads();
    const float* Bf = Bs + (size_t)f * RANK * RANK;
    float acc = 0.f;
    #pragma unroll 8
    for (int r = 0; r < RANK; ++r) acc += ta[r] * Bf[r * RANK + k];
    abh[(size_t)o * (NFAC * RANK) + f * RANK + k] = __float2half_rn(acc);
}

// ch[i, f*64+k] = fp16( C[f,k,i] )
__global__ void conv_c(const float* __restrict__ Cs, __half* __restrict__ ch) {
    int idx = blockIdx.x * 256 + threadIdx.x;
    int i = idx & (DIN - 1);
    int fk = idx >> 12;
    ch[(size_t)i * (NFAC * RANK) + fk] = __float2half_rn(Cs[idx]);
}

__global__ void conv_x(const float4* __restrict__ xi, __half2* __restrict__ xo) {
    size_t i = (size_t)blockIdx.x * 256 + threadIdx.x;
    float4 v = xi[i];
    xo[2 * i]     = __floats2half2_rn(v.x, v.y);
    xo[2 * i + 1] = __floats2half2_rn(v.z, v.w);
}

// D[128x256] tile of A[M,K] @ B[N,K]^T, fp16 in / fp32 accum. 512 thr, warp tile 64x32.
// EPI 0: fp32 out, += bias[n].  EPI 1: fp16 out, += addv[m,n] (full matrix).
template<int KTOT, int EPI>
__global__ void __launch_bounds__(512, 1)
gemm_hmma(const __half* __restrict__ A, const __half* __restrict__ B,
          const float* __restrict__ addv, void* __restrict__ outp, int ldo)
{
    constexpr int BM = 128, BN = 256, BK = 64, S = 4;
    constexpr int NCH = KTOT / BK;
    constexpr int ABYTES = BM * 128;          // 16 KB
    constexpr int BBYTES = BN * 128;          // 32 KB
    constexpr int STAGE = ABYTES + BBYTES;    // 48 KB

    extern __shared__ char smraw[];
    uint32_t sbase = (smem_u32(smraw) + 1023) & ~1023u;

    const int tid = threadIdx.x, wid = tid >> 5, lane = tid & 31;
    const int wm = wid & 1, wn = wid >> 1;    // 2 x 8 warp grid, 64x32 per warp
    const int m0 = blockIdx.y * BM, n0 = blockIdx.x * BN;
    const __half* Ab = A + (size_t)m0 * KTOT;
    const __half* Bb = B + (size_t)n0 * KTOT;

    auto load_chunk = [&](int p) {
        uint32_t s = sbase + (p % S) * STAGE;
        const __half* Ap = Ab + p * BK;
        const __half* Bp = Bb + p * BK;
        #pragma unroll
        for (int it = 0; it < 2; ++it) {      // A: 128 rows x 8 segs = 1024 cp16
            int idx = tid + it * 512;
            int r = idx >> 3, sg = idx & 7;
            cp16(s + SWZ((uint32_t)(r * 128 + sg * 16)), Ap + (size_t)r * KTOT + sg * 8);
        }
        #pragma unroll
        for (int it = 0; it < 4; ++it) {      // B: 256 rows x 8 segs = 2048 cp16
            int idx = tid + it * 512;
            int r = idx >> 3, sg = idx & 7;
            cp16(s + ABYTES + SWZ((uint32_t)(r * 128 + sg * 16)),
                 Bp + (size_t)r * KTOT + sg * 8);
        }
    };

    float acc[4][4][4];
    #pragma unroll
    for (int t = 0; t < 4; ++t)
        #pragma unroll
        for (int j = 0; j < 4; ++j)
            #pragma unroll
            for (int q = 0; q < 4; ++q) acc[t][j][q] = 0.f;

    #pragma unroll
    for (int p = 0; p < S - 1; ++p) {
        if (p < NCH) load_chunk(p);
        asm volatile("cp.async.commit_group;" ::: "memory");
    }

    const int la = lane & 15, lb = lane >> 4;

    for (int c = 0; c < NCH; ++c) {
        asm volatile("cp.async.wait_group %0;" :: "n"(S - 2) : "memory");
        __syncthreads();
        int p = c + S - 1;
        if (p < NCH) load_chunk(p);
        asm volatile("cp.async.commit_group;" ::: "memory");

        uint32_t sA = sbase + (c % S) * STAGE;
        uint32_t sB = sA + ABYTES;
        #pragma unroll
        for (int ks = 0; ks < 4; ++ks) {      // K = 4 x 16
            uint32_t af[4][4], bf[2][4];
            #pragma unroll
            for (int t = 0; t < 4; ++t) {
                uint32_t row = (uint32_t)(wm * 64 + t * 16 + la);
                ldsm4(af[t], sA + SWZ(row * 128 + (uint32_t)(ks * 32 + lb * 16)));
            }
            #pragma unroll
            for (int u = 0; u < 2; ++u) {
                uint32_t row = (uint32_t)(wn * 32 + u * 16 + la);
                ldsm4(bf[u], sB + SWZ(row * 128 + (uint32_t)(ks * 32 + lb * 16)));
            }
            #pragma unroll
            for (int t = 0; t < 4; ++t)
                #pragma unroll
                for (int u = 0; u < 2; ++u) {
                    hmma(acc[t][2 * u],     af[t], bf[u][0], bf[u][2]);
                    hmma(acc[t][2 * u + 1], af[t], bf[u][1], bf[u][3]);
                }
        }
    }

    // epilogue (register accumulators -> global)
    const int r0 = lane >> 2, c0 = (lane & 3) * 2;
    #pragma unroll
    for (int t = 0; t < 4; ++t) {
        #pragma unroll
        for (int h = 0; h < 2; ++h) {
            size_t row = (size_t)(m0 + wm * 64 + t * 16 + h * 8 + r0);
            #pragma unroll
            for (int j = 0; j < 4; ++j) {
                int col = n0 + wn * 32 + j * 8 + c0;
                float v0 = acc[t][j][h * 2 + 0], v1 = acc[t][j][h * 2 + 1];
                if (EPI == 0) {
                    float2 w;
                    w.x = v0 + addv[col];
                    w.y = v1 + addv[col + 1];
                    *(float2*)((float*)outp + row * (size_t)ldo + col) = w;
                } else {
                    const float* wr = addv + row * (size_t)ldo + col;
                    *(__half2*)((__half*)outp + row * (size_t)ldo + col) =
                        __floats2half2_rn(v0 + wr[0], v1 + wr[1]);
                }
            }
        }
    }
}

extern "C" void kernel_launch(void* const* d_in, const int* in_sizes, int n_in,
                              void* d_out, int out_size) {
    (void)in_sizes; (void)n_in; (void)out_size;
    const float* x    = (const float*)d_in[0];
    const float* W    = (const float*)d_in[1];
    const float* bias = (const float*)d_in[2];
    const float* As   = (const float*)d_in[3];
    const float* Bs   = (const float*)d_in[4];
    const float* Cs   = (const float*)d_in[5];

    __half *xh, *weff, *abh, *ch;
    cudaGetSymbolAddress((void**)&xh,   g_xh);
    cudaGetSymbolAddress((void**)&weff, g_weff);
    cudaGetSymbolAddress((void**)&abh,  g_abh);
    cudaGetSymbolAddress((void**)&ch,   g_ch);

    const int SMEM_SZ = 1024 + 4 * (128 * 128 + 256 * 128);  // 197632 B
    cudaFuncSetAttribute(gemm_hmma<128, 1>,
                         cudaFuncAttributeMaxDynamicSharedMemorySize, SMEM_SZ);
    cudaFuncSetAttribute(gemm_hmma<4096, 0>,
                         cudaFuncAttributeMaxDynamicSharedMemorySize, SMEM_SZ);

    prep_ab<<<dim3(DOUT, NFAC), RANK>>>(As, Bs, abh);
    conv_c<<<(NFAC * RANK * DIN) / 256, 256>>>(Cs, ch);
    conv_x<<<(TOKENS * (DIN / 4)) / 256, 256>>>((const float4*)x, (__half2*)xh);
    // W_eff = W + abh @ ch^T   (M=DOUT, N=DIN, K=128), fp16 out
    gemm_hmma<128, 1><<<dim3(DIN / 256, DOUT / 128), 512, SMEM_SZ>>>(
        abh, ch, W, (void*)weff, DIN);
    // out = xh @ weff^T + bias (M=TOKENS, N=DOUT, K=DIN), fp32 out
    gemm_hmma<4096, 0><<<dim3(DOUT / 256, TOKENS / 128), 512, SMEM_SZ>>>(
        xh, weff, bias, d_out, DOUT);
}